// round 17
// baseline (speedup 1.0000x reference)
#include <cuda_runtime.h>
#include <cstdint>

#define BB 32
#define TT 2048
#define LL 17
#define EE 128
#define VV 100000
#define SS 128        // chunk length for backtracking
#define CC 16         // number of chunks (TT / SS)

// Scratch
__device__ float g_em[BB * TT * LL + 512];      // emissions (+pad for prefetch overrun)
__device__ float g_alpha[BB * TT * LL];         // forward alphas
__device__ unsigned char g_comp[BB * CC * LL];  // chunk survivor maps
__device__ unsigned char g_tag17[BB * CC * SS * LL]; // per-chunk tags for ALL 17 seeds

// a + b via FFMA imm-1.0 (exact, single rounding == FADD).
__device__ __forceinline__ float fadd1(float a, float b) {
    float r;
    asm("fma.rn.f32 %0, %1, 0f3F800000, %2;" : "=f"(r) : "f"(a), "f"(b));
    return r;
}

__device__ __forceinline__ void fma4(float4& a, float xe, const float4 w) {
    a.x += xe * w.x; a.y += xe * w.y; a.z += xe * w.z; a.w += xe * w.w;
}

// Max-only step (max exactly associative -> bitwise reference value).
__device__ __forceinline__ float step_max(float alpha, const float* trc) {
    float s[LL];
#pragma unroll
    for (int j = 0; j < LL; j++)
        s[j] = fadd1(__shfl_sync(0xFFFFFFFFu, alpha, j), trc[j]);
    float v[9];
#pragma unroll
    for (int k = 0; k < 8; k++) v[k] = fmaxf(s[2 * k], s[2 * k + 1]);
    v[8] = s[16];
#pragma unroll
    for (int k = 0; k < 4; k++) v[k] = fmaxf(v[2 * k], v[2 * k + 1]);
    v[0] = fmaxf(v[0], v[1]); v[2] = fmaxf(v[2], v[3]);
    v[0] = fmaxf(v[0], v[2]);
    return fmaxf(v[0], v[8]);
}

// ---------------------------------------------------------------------------
// Fused emissions + forward. One block per batch, 256 threads.
//   warps 0-6 (224 thr): produce em[b][t] in 224-token waves, in order;
//     after each wave: bar.sync(1,224) -> tid0 bumps smem token counter.
//   warp 7: the sequential forward chain (R4 design, bitwise-identical),
//     polling the counter before each 8-step block.
// CONSUMER reads g_em via __ldcg (L2-coherent). R15's bug: __ldg's
// non-coherent path served lines cached before producers wrote them.
// No deadlock: producers never wait on the consumer; counter is monotonic;
// each block is independent and single-SM resident.
// ---------------------------------------------------------------------------
__global__ void __launch_bounds__(256, 1) fwdfused_kernel(
    const void* __restrict__ textp,
    const float* __restrict__ emb,
    const float* __restrict__ W5,
    const float* __restrict__ b5,
    const float* __restrict__ trans)
{
    __shared__ float sW[EE * 20];
    __shared__ float sb[20];
    __shared__ volatile int s_tokens;    // produced-token count (monotonic)

    const int tid = threadIdx.x;
    const int b = blockIdx.x;

    // dtype detection: all of first 512 u64 words < V <=> int64 storage
    const unsigned long long* t64 = (const unsigned long long*)textp;
    int ok = 1;
    for (int i = tid; i < 512; i += 256)
        if (t64[i] >= (unsigned long long)VV) ok = 0;

    for (int i = tid; i < EE * 20; i += 256) sW[i] = 0.0f;
    if (tid < 20) sb[tid] = 0.0f;
    if (tid == 0) s_tokens = 0;
    int is64 = __syncthreads_and(ok);
    for (int i = tid; i < EE * LL; i += 256) {
        int e = i / LL, l = i % LL;
        sW[e * 20 + l] = W5[i];
    }
    if (tid < LL) sb[tid] = b5[tid];
    __syncthreads();

    if (tid < 224) {
        // ===================== producer warps 0-6 =====================
        for (int base = 0; base < TT; base += 224) {
            int t = base + tid;
            if (t < TT) {
                int token = b * TT + t;
                int idx;
                if (is64) idx = (int)((const unsigned long long*)textp)[token];
                else      idx = ((const int*)textp)[token];
                idx = max(0, min(VV - 1, idx));

                const float4* row = (const float4*)(emb + (size_t)idx * EE);
                float4 a0 = *(const float4*)&sb[0];
                float4 a1 = *(const float4*)&sb[4];
                float4 a2 = *(const float4*)&sb[8];
                float4 a3 = *(const float4*)&sb[12];
                float4 a4 = *(const float4*)&sb[16];

#pragma unroll 4
                for (int e4 = 0; e4 < EE / 4; e4++) {
                    float4 x = __ldg(&row[e4]);
                    const float* wb = &sW[e4 * 4 * 20];
#pragma unroll
                    for (int c = 0; c < 4; c++) {
                        float xe = (c == 0) ? x.x : (c == 1) ? x.y : (c == 2) ? x.z : x.w;
                        const float4* w4 = (const float4*)(wb + c * 20);
                        fma4(a0, xe, w4[0]);
                        fma4(a1, xe, w4[1]);
                        fma4(a2, xe, w4[2]);
                        fma4(a3, xe, w4[3]);
                        fma4(a4, xe, w4[4]);
                    }
                }

                float* o = g_em + (size_t)token * LL;
                o[0] = a0.x; o[1] = a0.y; o[2] = a0.z; o[3] = a0.w;
                o[4] = a1.x; o[5] = a1.y; o[6] = a1.z; o[7] = a1.w;
                o[8] = a2.x; o[9] = a2.y; o[10] = a2.z; o[11] = a2.w;
                o[12] = a3.x; o[13] = a3.y; o[14] = a3.z; o[15] = a3.w;
                o[16] = a4.x;
                __threadfence_block();
            }
            // producer-only barrier (224 = 7 warps); has memory semantics
            asm volatile("bar.sync 1, 224;" ::: "memory");
            if (tid == 0) s_tokens = (base + 224 < TT) ? (base + 224) : TT;
        }
        return;
    }

    // ======================== forward warp (wid 7) ========================
    const int l = tid - 224;
    const int le = (l < LL) ? l : 0;
    const bool act = (l < LL);

    float trc[LL];
#pragma unroll
    for (int j = 0; j < LL; j++) trc[j] = act ? trans[j * LL + le] : 0.0f;

    // wait for rows 0..16
    while (s_tokens < 17) __nanosleep(100);
    __threadfence_block();

    const float* em = g_em + (size_t)b * TT * LL;
    float alpha = act ? __ldcg(em + le) : -3.0e38f;   // .cg: L2-coherent
    float* pa = g_alpha + (size_t)b * TT * LL + l;
    if (act) pa[0] = alpha;

    float ring[8];
#pragma unroll
    for (int i = 0; i < 8; i++) ring[i] = __ldcg(em + (1 + i) * LL + le);
    const float* pf = em + 9 * LL + le;
    float* ps = pa + LL;

    // t = 1 .. 2040 in 255 blocks of 8
    for (int blk = 0; blk < 255; blk++) {
        int need = 8 * blk + 17;                  // rows consumed/prefetched this blk
        if (need > TT) need = TT;
        if (s_tokens < need) {
            while (s_tokens < need) __nanosleep(60);
            __threadfence_block();
        }
#pragma unroll
        for (int u = 0; u < 8; u++) {
            float emc = ring[u];
            ring[u] = __ldcg(pf + u * LL);        // t+8, L2-coherent (pad covers overrun)
            alpha = fadd1(step_max(alpha, trc), emc);
            if (act) ps[u * LL] = alpha;
        }
        pf += 8 * LL;
        ps += 8 * LL;
    }
    // tail t = 2041..2047
#pragma unroll
    for (int u = 0; u < 7; u++) {
        alpha = fadd1(step_max(alpha, trc), ring[u]);
        if (act) ps[u * LL] = alpha;
    }
}

// ---------------------------------------------------------------------------
// argmax over 17 values, FIRST-index tie-break (matches jnp.argmax).
// ---------------------------------------------------------------------------
__device__ __forceinline__ void argmax17(const float* s, float& bv, int& bi) {
    float v[9]; int ix[9];
#pragma unroll
    for (int k = 0; k < 8; k++) {
        bool g = s[2 * k + 1] > s[2 * k];
        v[k]  = g ? s[2 * k + 1] : s[2 * k];
        ix[k] = g ? 2 * k + 1 : 2 * k;
    }
    v[8] = s[16]; ix[8] = 16;
#pragma unroll
    for (int k = 0; k < 4; k++) {
        bool g = v[2 * k + 1] > v[2 * k];
        v[k]  = g ? v[2 * k + 1] : v[2 * k];
        ix[k] = g ? ix[2 * k + 1] : ix[2 * k];
    }
    { bool g = v[1] > v[0]; v[0] = g ? v[1] : v[0]; ix[0] = g ? ix[1] : ix[0]; }
    { bool g = v[3] > v[2]; v[2] = g ? v[3] : v[2]; ix[2] = g ? ix[3] : ix[2]; }
    { bool g = v[2] > v[0]; v[0] = g ? v[2] : v[0]; ix[0] = g ? ix[2] : ix[0]; }
    { bool g = v[8] > v[0]; v[0] = g ? v[8] : v[0]; ix[0] = g ? ix[8] : ix[0]; }
    bv = v[0]; bi = ix[0];
}

// ---------------------------------------------------------------------------
// bp_kernel: per (b, chunk). Recompute exact backpointers from stored
// alphas, walk ALL 17 seeds recording the tag sequence -> g_tag17, plus the
// chunk composition map -> g_comp.
// ---------------------------------------------------------------------------
__global__ void __launch_bounds__(256) bp_kernel(const float* __restrict__ trans)
{
    __shared__ float aS[(SS + 1) * LL];
    __shared__ float tS[LL * LL];
    __shared__ unsigned char bpS[SS * LL];
    __shared__ unsigned char tag17S[SS * LL];

    const int tid = threadIdx.x;
    const int b = blockIdx.x / CC, c = blockIdx.x % CC;
    const int t0 = c * SS;
    const int nrows = (c == CC - 1) ? SS : (SS + 1);
    const int nbp   = (c == CC - 1) ? (SS - 1) : SS;

    const float* src = g_alpha + ((size_t)b * TT + t0) * LL;
    for (int i = tid; i < nrows * LL; i += 256) aS[i] = src[i];
    for (int i = tid; i < LL * LL; i += 256) tS[i] = trans[i];
    __syncthreads();

    if (tid < 2 * nbp) {
        const int t = tid >> 1;
        const int h = tid & 1;
        float a[LL];
#pragma unroll
        for (int k = 0; k < LL; k++) a[k] = aS[t * LL + k];
        const int l0 = h ? 9 : 0;
        const int l1 = h ? LL : 9;
#pragma unroll 1
        for (int lcur = l0; lcur < l1; lcur++) {
            float s[LL];
#pragma unroll
            for (int k = 0; k < LL; k++) s[k] = a[k] + tS[k * LL + lcur];
            float bv; int bi2;
            argmax17(s, bv, bi2);
            bpS[t * LL + lcur] = (unsigned char)bi2;
        }
    }
    __syncthreads();

    if (tid < LL) {   // walk all 17 seeds, record every intermediate tag
        int cur = tid;
        for (int i = nbp - 1; i >= 0; i--) {
            cur = bpS[i * LL + cur];
            tag17S[i * LL + tid] = (unsigned char)cur;
        }
        g_comp[(b * CC + c) * LL + tid] = (unsigned char)cur;
    }
    __syncthreads();

    unsigned char* tdst = g_tag17 + ((size_t)(b * CC + c) * SS) * LL;
    for (int i = tid; i < nbp * LL; i += 256) tdst[i] = tag17S[i];
}

// ---------------------------------------------------------------------------
// tags_kernel: per (b, chunk). Derive the chunk seed via the comp-map
// chain, then pure table lookup into g_tag17. Block c==0 writes score/lens.
// ---------------------------------------------------------------------------
__global__ void __launch_bounds__(128) tags_kernel(float* __restrict__ out)
{
    __shared__ unsigned char compS[CC * LL];
    __shared__ float afin[LL];
    __shared__ int seedS;

    const int tid = threadIdx.x;
    const int b = blockIdx.x / CC, c = blockIdx.x % CC;
    const int t0 = c * SS;
    const int nbp = (c == CC - 1) ? (SS - 1) : SS;

    for (int i = tid; i < CC * LL; i += 128) compS[i] = g_comp[b * CC * LL + i];
    if (tid < LL) afin[tid] = g_alpha[((size_t)b * TT + TT - 1) * LL + tid];
    __syncthreads();

    if (tid == 0) {
        float bv = afin[0]; int bi = 0;
        for (int j = 1; j < LL; j++) if (afin[j] > bv) { bv = afin[j]; bi = j; }
        if (c == 0) {
            out[BB * TT + b] = bv;
            out[BB * TT + BB + b] = (float)TT;
        }
        int cur = bi;                       // tag at t = 2047
        for (int cc = CC - 1; cc >= c + 1; cc--) cur = compS[cc * LL + cur];
        seedS = cur;                        // tag at t = 128*(c+1) (or 2047 if c==15)
    }
    __syncthreads();

    const int seed = seedS;
    const unsigned char* tsrc = g_tag17 + ((size_t)(b * CC + c) * SS) * LL;
    float val = (tid < nbp) ? (float)tsrc[tid * LL + seed] : (float)seed;
    out[(size_t)b * TT + t0 + tid] = val;
}

// ---------------------------------------------------------------------------
extern "C" void kernel_launch(void* const* d_in, const int* in_sizes, int n_in,
                              void* d_out, int out_size)
{
    (void)in_sizes; (void)n_in; (void)out_size;
    const void*  text  = d_in[0];
    const float* emb   = (const float*)d_in[1];
    const float* W5    = (const float*)d_in[2];
    const float* b5    = (const float*)d_in[3];
    const float* trans = (const float*)d_in[4];
    float* out = (float*)d_out;

    fwdfused_kernel<<<BB, 256>>>(text, emb, W5, b5, trans);
    bp_kernel<<<BB * CC, 256>>>(trans);
    tags_kernel<<<BB * CC, 128>>>(out);
}